// round 15
// baseline (speedup 1.0000x reference)
#include <cuda_runtime.h>

#define NT 4096
#define RING_ROW 257           // float4 per ring row (bank-pad)
#define STAGE_STEPS 256

// ---- dynamic smem layout (bytes) ----
#define OFF_RING   0
#define F4_RING    (2*2*8*RING_ROW)                 // 4 stages x 8 rows x 257
#define OFF_CB     (F4_RING*16)                     // 131584
#define OFF_SF     (OFF_CB + 2*256*16*4)            // +32768 -> 164352
#define OFF_SIK    (OFF_SF + 42*16)                 // 165024
#define OFF_SB     (OFF_SIK + 18*16)                // 165312
#define OFF_WSUM   (OFF_SB + 8*16)                  // 165440
#define OFF_FLAGS  (OFF_WSUM + 2*8*16*4)            // 166464
#define SMEM_TOTAL (OFF_FLAGS + 32)                 // 166496

static __device__ __forceinline__ float tanha(float x) {
    float y; asm("tanh.approx.f32 %0, %1;" : "=f"(y) : "f"(x)); return y;
}
static __device__ __forceinline__ float sigm(float x) {
    return fmaf(tanha(0.5f * x), 0.5f, 0.5f);
}
static __device__ __forceinline__ void poll_ge(volatile int* p, int v) {
    if (*p >= v) return;
    while (*p < v) __nanosleep(64);
}

#define FMA4(acc, s, v) do { \
    (acc).x = fmaf((s), (v).x, (acc).x); (acc).y = fmaf((s), (v).y, (acc).y); \
    (acc).z = fmaf((s), (v).z, (acc).z); (acc).w = fmaf((s), (v).w, (acc).w); } while (0)

extern __shared__ __align__(16) unsigned char smem_raw[];

__global__ void __launch_bounds__(576, 1) mega_kernel(
    const float* __restrict__ inp,   // (256, 4096, 3)
    const float* __restrict__ ik,    // (3, 24)
    const float* __restrict__ rk,    // (8, 24)
    const float* __restrict__ fk,    // (21, 8)
    const float* __restrict__ bias,  // (32)
    float* __restrict__ out)         // (256, 4096, 8)
{
    float4* ring = (float4*)(smem_raw + OFF_RING);
    float*  cb   = (float*)(smem_raw + OFF_CB);      // [2][256][16]
    float4* sF4  = (float4*)(smem_raw + OFF_SF);
    float4* sIk4 = (float4*)(smem_raw + OFF_SIK);
    float4* sB4  = (float4*)(smem_raw + OFF_SB);
    float*  wsum = (float*)(smem_raw + OFF_WSUM);    // [2][8][16]
    volatile int* vfull  = (volatile int*)(smem_raw + OFF_FLAGS);      // [2][2]
    volatile int* vempty = (volatile int*)(smem_raw + OFF_FLAGS + 16); // [2][2]

    const int tid = threadIdx.x;
    if (tid < 42)      sF4[tid]     = ((const float4*)fk)[tid];
    else if (tid < 60) sIk4[tid-42] = ((const float4*)ik)[tid-42];
    else if (tid < 68) sB4[tid-60]  = ((const float4*)bias)[tid-60];
    if (tid >= 68 && tid < 76) ((int*)(smem_raw + OFF_FLAGS))[tid-68] = 0;
    __syncthreads();    // the ONLY block-wide barrier

    const float DX0 = 1.0f / 4095.0f;

    if (tid < 512) {
        // ==================== PRODUCER ====================
        const int g = tid >> 8, gtid = tid & 255;
        const int b = blockIdx.x * 2 + g;
        const int barid = 1 + g;
        const float* __restrict__ xb = inp + (size_t)b * NT * 3;
        float* __restrict__ cbg = cb + g * 256 * 16;
        float* __restrict__ wsg = wsum + g * 8 * 16;

        // ---- scan: 16 steps per thread ----
        float T[16];
#pragma unroll
        for (int c = 0; c < 16; c++) T[c] = 0.f;
        const int t0 = gtid * 16;
        {
            int tm = t0 - 1; if (tm < 0) tm = 0;
            float a0 = xb[tm*3], a1 = xb[tm*3+1], a2 = xb[tm*3+2];
#pragma unroll
            for (int k = 0; k < 16; k++) {
                const int s = t0 + k;
                const float* p = xb + s * 3;
                float n0 = p[0], n1 = p[1], n2 = p[2];
                const float w = (s >= 1) ? 1.f : 0.f;
                float d1 = (n0-a0)*w, d2 = (n1-a1)*w, d3 = (n2-a2)*w, d0 = DX0*w;
                float pb0 = ((float)s - 0.5f) * DX0;
                float pb1 = 0.5f*(n0+a0), pb2 = 0.5f*(n1+a1), pb3 = 0.5f*(n2+a2);
                T[0] =fmaf(pb0,d0,T[0]);  T[1] =fmaf(pb0,d1,T[1]);  T[2] =fmaf(pb0,d2,T[2]);  T[3] =fmaf(pb0,d3,T[3]);
                T[4] =fmaf(pb1,d0,T[4]);  T[5] =fmaf(pb1,d1,T[5]);  T[6] =fmaf(pb1,d2,T[6]);  T[7] =fmaf(pb1,d3,T[7]);
                T[8] =fmaf(pb2,d0,T[8]);  T[9] =fmaf(pb2,d1,T[9]);  T[10]=fmaf(pb2,d2,T[10]); T[11]=fmaf(pb2,d3,T[11]);
                T[12]=fmaf(pb3,d0,T[12]); T[13]=fmaf(pb3,d1,T[13]); T[14]=fmaf(pb3,d2,T[14]); T[15]=fmaf(pb3,d3,T[15]);
                a0 = n0; a1 = n1; a2 = n2;
            }
        }
        float inc[16];
#pragma unroll
        for (int c = 0; c < 16; c++) inc[c] = T[c];
        const int lane = gtid & 31, wid = gtid >> 5;   // 8 warps per group
#pragma unroll
        for (int off = 1; off < 32; off <<= 1) {
#pragma unroll
            for (int c = 0; c < 16; c++) {
                float v = __shfl_up_sync(0xffffffffu, inc[c], off);
                if (lane >= off) inc[c] += v;
            }
        }
        if (lane == 31) {
#pragma unroll
            for (int c = 0; c < 16; c++) wsg[wid*16 + c] = inc[c];
        }
        asm volatile("bar.sync %0, %1;" :: "r"(barid), "r"(256) : "memory");
        if (gtid < 16) {
            float run = 0.f;
            for (int wv = 0; wv < 8; wv++) { float v = wsg[wv*16 + gtid]; wsg[wv*16 + gtid] = run; run += v; }
        }
        asm volatile("bar.sync %0, %1;" :: "r"(barid), "r"(256) : "memory");
#pragma unroll
        for (int c = 0; c < 16; c++) cbg[gtid*16 + c] = wsg[wid*16 + c] + (inc[c] - T[c]);
        asm volatile("bar.sync %0, %1;" :: "r"(barid), "r"(256) : "memory");

        const float bx0 = xb[0], bx1 = xb[1], bx2 = xb[2];

        // ---- emit: 16 rounds of 256 steps into the 2-stage ring ----
        for (int r = 0; r < 16; r++) {
            const int st = r & 1, w = r >> 1;
            if (w > 0) { poll_ge(&vempty[g*2 + st], w); __threadfence_block(); }
            const int s = r * 256 + gtid;
            const int chunk = s >> 4;
            float C[16];
#pragma unroll
            for (int c = 0; c < 16; c++) C[c] = cbg[chunk*16 + c];
            {
                const int tc0 = chunk * 16;
                int tm = tc0 - 1; if (tm < 0) tm = 0;
                float a0 = xb[tm*3], a1 = xb[tm*3+1], a2 = xb[tm*3+2];
#pragma unroll
                for (int k0 = 0; k0 < 16; k0++) {
                    const int k = tc0 + k0;
                    const float* p = xb + k * 3;
                    float n0 = p[0], n1 = p[1], n2 = p[2];
                    const float wv = (k >= 1 && k <= s) ? 1.f : 0.f;
                    float d1 = (n0-a0)*wv, d2 = (n1-a1)*wv, d3 = (n2-a2)*wv, d0 = DX0*wv;
                    float pb0 = ((float)k - 0.5f) * DX0;
                    float pb1 = 0.5f*(n0+a0), pb2 = 0.5f*(n1+a1), pb3 = 0.5f*(n2+a2);
                    C[0] =fmaf(pb0,d0,C[0]);  C[1] =fmaf(pb0,d1,C[1]);  C[2] =fmaf(pb0,d2,C[2]);  C[3] =fmaf(pb0,d3,C[3]);
                    C[4] =fmaf(pb1,d0,C[4]);  C[5] =fmaf(pb1,d1,C[5]);  C[6] =fmaf(pb1,d2,C[6]);  C[7] =fmaf(pb1,d3,C[7]);
                    C[8] =fmaf(pb2,d0,C[8]);  C[9] =fmaf(pb2,d1,C[9]);  C[10]=fmaf(pb2,d2,C[10]); C[11]=fmaf(pb2,d3,C[11]);
                    C[12]=fmaf(pb3,d0,C[12]); C[13]=fmaf(pb3,d1,C[13]); C[14]=fmaf(pb3,d2,C[14]); C[15]=fmaf(pb3,d3,C[15]);
                    a0 = n0; a1 = n1; a2 = n2;
                }
            }
            const float xs0 = xb[s*3], xs1 = xb[s*3+1], xs2 = xb[s*3+2];
            float L1_0 = (float)s * DX0;
            float L1_1 = xs0 - bx0, L1_2 = xs1 - bx1, L1_3 = xs2 - bx2;
            float sg[21];
            sg[0] = 1.f;
            sg[1] = L1_0; sg[2] = L1_1; sg[3] = L1_2; sg[4] = L1_3;
            sg[5]  = C[0];                  sg[6]  = C[1];                  sg[7]  = C[2];                  sg[8]  = C[3];
            sg[9]  = fmaf(-bx0,L1_0,C[4]);  sg[10] = fmaf(-bx0,L1_1,C[5]);  sg[11] = fmaf(-bx0,L1_2,C[6]);  sg[12] = fmaf(-bx0,L1_3,C[7]);
            sg[13] = fmaf(-bx1,L1_0,C[8]);  sg[14] = fmaf(-bx1,L1_1,C[9]);  sg[15] = fmaf(-bx1,L1_2,C[10]); sg[16] = fmaf(-bx1,L1_3,C[11]);
            sg[17] = fmaf(-bx2,L1_0,C[12]); sg[18] = fmaf(-bx2,L1_1,C[13]); sg[19] = fmaf(-bx2,L1_2,C[14]); sg[20] = fmaf(-bx2,L1_3,C[15]);
            float norm = 1.0f;
            if (s >= 1) norm = __fdividef(4095.0f, (float)s);
            else {
#pragma unroll
                for (int c2 = 1; c2 < 21; c2++) sg[c2] = 0.f;
            }
            float4 aA = make_float4(0.f,0.f,0.f,0.f), aB = make_float4(0.f,0.f,0.f,0.f);
#pragma unroll
            for (int c2 = 0; c2 < 21; c2++) {
                float sc = sg[c2];
                FMA4(aA, sc, sF4[2*c2]);
                FMA4(aB, sc, sF4[2*c2+1]);
            }
            float fg0 = sigm(fmaf(aA.x, norm, sB4[2].x));
            float fg1 = sigm(fmaf(aA.y, norm, sB4[2].y));
            float fg2 = sigm(fmaf(aA.z, norm, sB4[2].z));
            float fg3 = sigm(fmaf(aA.w, norm, sB4[2].w));
            float fg4 = sigm(fmaf(aB.x, norm, sB4[3].x));
            float fg5 = sigm(fmaf(aB.y, norm, sB4[3].y));
            float fg6 = sigm(fmaf(aB.z, norm, sB4[3].z));
            float fg7 = sigm(fmaf(aB.w, norm, sB4[3].w));

            float4 xiA = sB4[0], xiB = sB4[1], xgA = sB4[4], xgB = sB4[5], xoA = sB4[6], xoB = sB4[7];
            FMA4(xiA, xs0, sIk4[0]);  FMA4(xiB, xs0, sIk4[1]);
            FMA4(xgA, xs0, sIk4[2]);  FMA4(xgB, xs0, sIk4[3]);
            FMA4(xoA, xs0, sIk4[4]);  FMA4(xoB, xs0, sIk4[5]);
            FMA4(xiA, xs1, sIk4[6]);  FMA4(xiB, xs1, sIk4[7]);
            FMA4(xgA, xs1, sIk4[8]);  FMA4(xgB, xs1, sIk4[9]);
            FMA4(xoA, xs1, sIk4[10]); FMA4(xoB, xs1, sIk4[11]);
            FMA4(xiA, xs2, sIk4[12]); FMA4(xiB, xs2, sIk4[13]);
            FMA4(xgA, xs2, sIk4[14]); FMA4(xgB, xs2, sIk4[15]);
            FMA4(xoA, xs2, sIk4[16]); FMA4(xoB, xs2, sIk4[17]);

            float4* rg = ring + (size_t)((g*2 + st) * 8) * RING_ROW + gtid;
            rg[0*RING_ROW] = make_float4(0.5f*xiA.x, xgA.x, 0.5f*xoA.x, fg0);
            rg[1*RING_ROW] = make_float4(0.5f*xiA.y, xgA.y, 0.5f*xoA.y, fg1);
            rg[2*RING_ROW] = make_float4(0.5f*xiA.z, xgA.z, 0.5f*xoA.z, fg2);
            rg[3*RING_ROW] = make_float4(0.5f*xiA.w, xgA.w, 0.5f*xoA.w, fg3);
            rg[4*RING_ROW] = make_float4(0.5f*xiB.x, xgB.x, 0.5f*xoB.x, fg4);
            rg[5*RING_ROW] = make_float4(0.5f*xiB.y, xgB.y, 0.5f*xoB.y, fg5);
            rg[6*RING_ROW] = make_float4(0.5f*xiB.z, xgB.z, 0.5f*xoB.z, fg6);
            rg[7*RING_ROW] = make_float4(0.5f*xiB.w, xgB.w, 0.5f*xoB.w, fg7);

            asm volatile("bar.sync %0, %1;" :: "r"(barid), "r"(256) : "memory");
            if (gtid == 0) vfull[g*2 + st] = w + 1;
        }
    } else {
        // ==================== CONSUMER (LSTM recurrence) ====================
        const int cw = (tid - 512) >> 5;          // 0 or 1 -> batch parity
        const int lane = tid & 31;
        const int u = lane & 7;
        const bool active = lane < 8;
        const int b = blockIdx.x * 2 + cw;

        const float Ri0=0.5f*rk[0*24+u], Ri1=0.5f*rk[1*24+u], Ri2=0.5f*rk[2*24+u], Ri3=0.5f*rk[3*24+u];
        const float Ri4=0.5f*rk[4*24+u], Ri5=0.5f*rk[5*24+u], Ri6=0.5f*rk[6*24+u], Ri7=0.5f*rk[7*24+u];
        const float Rc0=rk[0*24+8+u], Rc1=rk[1*24+8+u], Rc2=rk[2*24+8+u], Rc3=rk[3*24+8+u];
        const float Rc4=rk[4*24+8+u], Rc5=rk[5*24+8+u], Rc6=rk[6*24+8+u], Rc7=rk[7*24+8+u];
        const float Ro0=0.5f*rk[0*24+16+u], Ro1=0.5f*rk[1*24+16+u], Ro2=0.5f*rk[2*24+16+u], Ro3=0.5f*rk[3*24+16+u];
        const float Ro4=0.5f*rk[4*24+16+u], Ro5=0.5f*rk[5*24+16+u], Ro6=0.5f*rk[6*24+16+u], Ro7=0.5f*rk[7*24+16+u];

        float* __restrict__ op = out + (size_t)b * NT * 8 + u;
        float h = 0.f, c = 0.f;      // t=0 folds into the generic step (h=c=0)

        for (int r = 0; r < 16; r++) {
            const int st = r & 1, w = r >> 1;
            poll_ge(&vfull[cw*2 + st], w + 1);
            __threadfence_block();
            const float4* __restrict__ sb = ring + (size_t)((cw*2 + st) * 8 + u) * RING_ROW;
#pragma unroll 1
            for (int jo = 0; jo < 8; jo++) {
                const float4* __restrict__ sbj = sb + jo * 32;
#pragma unroll
                for (int ji = 0; ji < 32; ji++) {
                    float4 gt = sbj[ji];
                    float h0 = __shfl_sync(0xffffffffu, h, 0, 8);
                    float h1 = __shfl_sync(0xffffffffu, h, 1, 8);
                    float h2 = __shfl_sync(0xffffffffu, h, 2, 8);
                    float h3 = __shfl_sync(0xffffffffu, h, 3, 8);
                    float h4 = __shfl_sync(0xffffffffu, h, 4, 8);
                    float h5 = __shfl_sync(0xffffffffu, h, 5, 8);
                    float h6 = __shfl_sync(0xffffffffu, h, 6, 8);
                    float h7 = __shfl_sync(0xffffffffu, h, 7, 8);
                    float fc = gt.w * c;
                    float i01 = fmaf(h1,Ri1, fmaf(h0,Ri0, gt.x));
                    float i23 = fmaf(h3,Ri3, h2*Ri2);
                    float i45 = fmaf(h5,Ri5, h4*Ri4);
                    float i67 = fmaf(h7,Ri7, h6*Ri6);
                    float gi = ((i01 + i23) + i45) + i67;
                    float c01 = fmaf(h1,Rc1, fmaf(h0,Rc0, gt.y));
                    float c23 = fmaf(h3,Rc3, h2*Rc2);
                    float c45 = fmaf(h5,Rc5, h4*Rc4);
                    float c67 = fmaf(h7,Rc7, h6*Rc6);
                    float gc = ((c01 + c23) + c45) + c67;
                    float o01 = fmaf(h1,Ro1, fmaf(h0,Ro0, gt.z));
                    float o23 = fmaf(h3,Ro3, h2*Ro2);
                    float o45 = fmaf(h5,Ro5, h4*Ro4);
                    float o67 = fmaf(h7,Ro7, h6*Ro6);
                    float go = ((o01 + o23) + o45) + o67;
                    float vi = fmaf(tanha(gi), 0.5f, 0.5f);
                    float vc = tanha(gc);
                    float vo = fmaf(tanha(go), 0.5f, 0.5f);
                    c = fmaf(vi, vc, fc);
                    h = vo * tanha(c);
                    if (active) *op = h;
                    op += 8;
                }
            }
            __syncwarp();
            if (lane == 0) vempty[cw*2 + st] = w + 1;
        }
    }
}

extern "C" void kernel_launch(void* const* d_in, const int* in_sizes, int n_in,
                              void* d_out, int out_size)
{
    const float* inp  = (const float*)d_in[0];   // inputs (256,4096,3)
    const float* ik   = (const float*)d_in[1];   // input_kernel (3,24)
    const float* rk   = (const float*)d_in[2];   // recurrent_kernel (8,24)
    const float* fk   = (const float*)d_in[3];   // forget_kernel (21,8)
    const float* bias = (const float*)d_in[4];   // bias (32)
    float* out = (float*)d_out;                  // (256,4096,8) f32

    cudaFuncSetAttribute(mega_kernel, cudaFuncAttributeMaxDynamicSharedMemorySize,
                         SMEM_TOTAL);
    mega_kernel<<<128, 576, SMEM_TOTAL>>>(inp, ik, rk, fk, bias, out);
}